// round 11
// baseline (speedup 1.0000x reference)
#include <cuda_runtime.h>
#include <cuda_bf16.h>
#include <stdint.h>

#define NB 4
#define NC 256
#define NHW 4096
#define NL 512

// ---------------- scratch (no allocations allowed) ----------------
__device__ float    g_Ql   [NB*NHW];
__device__ float    g_Qdis [NB*NHW];
__device__ float    g_Sdis [NB*NHW];
__device__ float    g_winv [NB*NHW];
__device__ float    g_qinv [NB*NHW];
__device__ float    g_qinvc[NB*NHW];
__device__ int      g_qdest[NB*NHW];
__device__ int      g_sdest[NB*NHW];
__device__ int      g_nq[NB], g_ns[NB];
__device__ int      g_sim  [NB*NHW];
__device__ uint32_t g_Ac[NB*NHW*(NC/2)];      // bf16: [b][i][k] row-major (compacted support, pre-scaled)
__device__ uint32_t g_Bc[NB*NHW*(NC/2)];      // bf16: [b][j][k] row-major (compacted query)

static __device__ __forceinline__ uint32_t packbf2(float lo, float hi) {
    __nv_bfloat162 t = __floats2bfloat162_rn(lo, hi);
    return *reinterpret_cast<uint32_t*>(&t);
}

#define CP_ASYNC16(dst, src) \
    asm volatile("cp.async.cg.shared.global [%0], [%1], 16;\n" :: "r"(dst), "l"(src))
#define CP_COMMIT() asm volatile("cp.async.commit_group;\n")
#define CP_WAIT1()  asm volatile("cp.async.wait_group 1;\n" ::: "memory")
#define CP_WAIT0()  asm volatile("cp.async.wait_group 0;\n" ::: "memory")

// ---------------- K1: labels, disrupt masks, column norms (parallel over C) ----------------
__global__ void k_prep(const float* __restrict__ Qf, const float* __restrict__ Sf,
                       const float* __restrict__ Qlab, const float* __restrict__ Slab,
                       const float* __restrict__ qbg, const float* __restrict__ sbg)
{
    __shared__ float sqs[8][33];
    __shared__ float sss[8][33];
    int blk = blockIdx.x;                  // NB*NHW/32 = 512
    int b   = blk >> 7;
    int q0  = (blk & 127) * 32;
    int tx  = threadIdx.x & 31, ty = threadIdx.x >> 5;
    int q   = q0 + tx;

    const float* Qp = Qf + ((size_t)b * NC + ty * 32) * NHW + q;
    const float* Sp = Sf + ((size_t)b * NC + ty * 32) * NHW + q;
    float sq = 0.f, ss = 0.f;
#pragma unroll
    for (int c = 0; c < 32; c++) {
        float v = Qp[(size_t)c * NHW]; sq += v * v;
        float u = Sp[(size_t)c * NHW]; ss += u * u;
    }
    sqs[ty][tx] = sq; sss[ty][tx] = ss;
    __syncthreads();

    if (ty == 0) {
        float tq = 0.f, ts = 0.f;
#pragma unroll
        for (int r = 0; r < 8; r++) { tq += sqs[r][tx]; ts += sss[r][tx]; }
        int idx = b * NHW + q;
        int h = q >> 6, w = q & 63;
        int lab = (h * 8) * NL + (w * 8);              // nearest resize 512->64
        float ql = Qlab[b * NL * NL + lab];
        float sl = Slab[b * NL * NL + lab];
        float qa = (qbg[(b * 2 + 1) * NHW + q] > qbg[(b * 2 + 0) * NHW + q]) ? 1.f : 0.f;
        float sa = (sbg[(b * 2 + 1) * NHW + q] > sbg[(b * 2 + 0) * NHW + q]) ? 1.f : 0.f;
        g_Ql[idx]   = ql;
        g_Qdis[idx] = fmaxf(1.f - qa - ql, 0.f);
        g_Sdis[idx] = fmaxf(1.f - sa - sl, 0.f);
        g_qinv[idx] = (tq > 0.f) ? 1.f / sqrtf(tq) : 0.f;
        g_winv[idx] = (sl != 0.f && ts > 0.f) ? 1.f / sqrtf(ts) : 0.f;
    }
}

// ---------------- K2: per-batch compaction via warp scans + pad/sim init ----------------
__global__ void k_compact()
{
    __shared__ int wq[32], ws[32];
    int b = blockIdx.x, tid = threadIdx.x;
    int lane = tid & 31, wid = tid >> 5;
    int base = b * NHW;

    int qf[4], sf[4];
    int lq = 0, ls = 0;
#pragma unroll
    for (int r = 0; r < 4; r++) {
        int idx = tid * 4 + r;
        qf[r] = (g_Ql[base + idx] == 1.0f);
        sf[r] = (g_winv[base + idx] > 0.f);
        lq += qf[r]; ls += sf[r];
    }
    // warp inclusive scan
    int iq = lq, is = ls;
#pragma unroll
    for (int off = 1; off < 32; off <<= 1) {
        int a = __shfl_up_sync(0xffffffffu, iq, off);
        int c = __shfl_up_sync(0xffffffffu, is, off);
        if (lane >= off) { iq += a; is += c; }
    }
    if (lane == 31) { wq[wid] = iq; ws[wid] = is; }
    __syncthreads();
    if (wid == 0) {
        int vq = wq[lane], vs = ws[lane];
#pragma unroll
        for (int off = 1; off < 32; off <<= 1) {
            int a = __shfl_up_sync(0xffffffffu, vq, off);
            int c = __shfl_up_sync(0xffffffffu, vs, off);
            if (lane >= off) { vq += a; vs += c; }
        }
        wq[lane] = vq; ws[lane] = vs;
    }
    __syncthreads();
    int qex = (wid ? wq[wid - 1] : 0) + iq - lq;
    int sex = (wid ? ws[wid - 1] : 0) + is - ls;
#pragma unroll
    for (int r = 0; r < 4; r++) {
        int idx = tid * 4 + r;
        if (qf[r]) { g_qdest[base + idx] = qex; g_qinvc[base + qex] = g_qinv[base + idx]; }
        else         g_qdest[base + idx] = -1;
        if (sf[r])   g_sdest[base + idx] = sex;
        else         g_sdest[base + idx] = -1;
        qex += qf[r]; sex += sf[r];
    }
    int nq = wq[31], ns = ws[31];
    if (tid == 0) { g_nq[b] = nq; g_ns[b] = ns; }

    for (int i = tid; i < NHW; i += 1024) g_sim[base + i] = 0;

    int nsp = (ns + 127) & ~127;
    for (int i = tid; i < (nsp - ns) * 128; i += 1024) {
        int row = ns + (i >> 7), kp = i & 127;
        g_Ac[((size_t)base + row) * 128 + kp] = 0;
    }
    int nqp = (nq + 127) & ~127;
    for (int i = tid; i < (nqp - nq) * 128; i += 1024) {
        int row = nq + (i >> 7), kp = i & 127;
        g_Bc[((size_t)base + row) * 128 + kp] = 0;
    }
}

// ---------------- K3: negatives + compacted bf16 operand packing ----------------
__global__ void k_pack(const float* __restrict__ Qf, const float* __restrict__ Sf,
                       float* __restrict__ neg, int write_neg)
{
    __shared__ float Qt[32][33];
    __shared__ float St[32][33];
    int b  = blockIdx.z;
    int q0 = blockIdx.x * 32;
    int c0 = blockIdx.y * 32;
    int tx = threadIdx.x, ty = threadIdx.y;

    const float* Qbase = Qf + ((size_t)b * NC + c0) * NHW + q0;
    const float* Sbase = Sf + ((size_t)b * NC + c0) * NHW + q0;
#pragma unroll
    for (int r = 0; r < 4; r++) {
        int c = ty + r * 8;
        Qt[c][tx] = Qbase[(size_t)c * NHW + tx];
        St[c][tx] = Sbase[(size_t)c * NHW + tx];
    }
    __syncthreads();

    if (write_neg) {
#pragma unroll
        for (int r = 0; r < 4; r++) {
            int ql = ty + r * 8;
            int q  = q0 + ql;
            float qd = g_Qdis[b * NHW + q];
            float sd = g_Sdis[b * NHW + q];
            neg[(((size_t)b * 2 + 0) * NHW + q) * NC + c0 + tx] = Qt[tx][ql] * qd;
            neg[(((size_t)b * 2 + 1) * NHW + q) * NC + c0 + tx] = St[tx][ql] * sd;
        }
    }
    int tid = ty * 32 + tx;
    // B operand: [b][j][kp] (compacted queries)
#pragma unroll
    for (int r = 0; r < 2; r++) {
        int ent = tid + r * 256;
        int sl  = ent >> 4;
        int kpl = ent & 15;
        int j = g_qdest[b * NHW + q0 + sl];
        if (j >= 0) {
            g_Bc[((size_t)b * NHW + j) * 128 + c0 / 2 + kpl] =
                packbf2(Qt[2 * kpl][sl], Qt[2 * kpl + 1][sl]);
        }
    }
    // A operand: [b][i][kp] (compacted support, pre-scaled by Sl/|S_col|)
#pragma unroll
    for (int r = 0; r < 2; r++) {
        int ent = tid + r * 256;
        int sl  = ent >> 4;
        int kpl = ent & 15;
        int i = g_sdest[b * NHW + q0 + sl];
        if (i >= 0) {
            float wv = g_winv[b * NHW + q0 + sl];
            g_Ac[((size_t)b * NHW + i) * 128 + c0 / 2 + kpl] =
                packbf2(St[2 * kpl][sl] * wv, St[2 * kpl + 1][sl] * wv);
        }
    }
}

// ---------------- K4: ldmatrix + cp.async bf16 mma GEMM, 64-k stages ----------------
// Tile 128x128, K=256 in 4 stages of 64 k. 3 buffers x 32KB = 96KB dynamic smem.
// Explicit 2-buffer FRAGMENT pipeline: LDSM of j+1 issued before MMAs of j, so
// shared-load latency is always covered by 16 in-flight MMAs. Register budget is
// deliberately >128 (no min-blocks bound) -> 1 CTA/SM, regs ~145, no spills.
__global__ void __launch_bounds__(256) k_gemm()
{
    extern __shared__ __align__(128) uint4 dsm[];

    int b  = blockIdx.z;
    int qt = blockIdx.x;
    int st = blockIdx.y;
    if (st * 128 >= g_ns[b] || qt * 128 >= g_nq[b]) return;

    int tid  = threadIdx.x;
    int warp = tid >> 5, lane = tid & 31;
    int wm = warp >> 2, wn = warp & 3;      // 2x4 warps -> 64x32 warp tiles
    int tc = lane & 3;

    float acc[4][4][4];
#pragma unroll
    for (int mi = 0; mi < 4; mi++)
#pragma unroll
        for (int ni = 0; ni < 4; ni++)
#pragma unroll
            for (int r = 0; r < 4; r++) acc[mi][ni][r] = 0.f;

    const uint4* gA = (const uint4*)(g_Ac + ((size_t)b * NHW + (size_t)st * 128) * 128);
    const uint4* gB = (const uint4*)(g_Bc + ((size_t)b * NHW + (size_t)qt * 128) * 128);

    uint32_t smem_base = (uint32_t)__cvta_generic_to_shared(dsm);
    const uint32_t B_OFF = 3 * 16384;       // B region after 3 A buffers

    // loader mapping: 2 threads/row, each 4 consecutive chunks (64B) per operand
    int lrow  = tid >> 1;
    int lhalf = (tid & 1) * 4;
    int lsw   = lrow & 7;
    const uint4* gArow = gA + (size_t)lrow * 32;
    const uint4* gBrow = gB + (size_t)lrow * 32;
    uint32_t sA = smem_base + lrow * 128;
    uint32_t sB = smem_base + B_OFF + lrow * 128;

#define ISSUE_STAGE(s, buf) do {                                            \
        uint32_t _o = (uint32_t)(buf) * 16384u;                             \
        _Pragma("unroll")                                                   \
        for (int i = 0; i < 4; i++)                                         \
            CP_ASYNC16(sA + _o + (uint32_t)(((lhalf + i) ^ lsw) << 4),      \
                       gArow + (s) * 8 + lhalf + i);                        \
        _Pragma("unroll")                                                   \
        for (int i = 0; i < 4; i++)                                         \
            CP_ASYNC16(sB + _o + (uint32_t)(((lhalf + i) ^ lsw) << 4),      \
                       gBrow + (s) * 8 + lhalf + i);                        \
        CP_COMMIT();                                                        \
    } while (0)

    ISSUE_STAGE(0, 0);
    ISSUE_STAGE(1, 1);

    // LDSM thread->address precompute
    int mt15 = lane & 15;                         // A row within 16 (mi adds 16)
    int akh  = lane >> 4;                         // A k-half (chunk parity)
    int asw  = mt15 & 7;
    uint32_t aBase = smem_base + (wm * 64 + mt15) * 128;
    int ntl  = wn * 32 + (lane & 7) + ((lane >> 4) & 1) * 8;  // B row (p adds 16)
    int bkh  = (lane >> 3) & 1;
    int bsw  = lane & 7;                          // ntl & 7 == lane & 7
    uint32_t bBase = smem_base + B_OFF + ntl * 128;

    uint32_t af[2][4][4];       // [frag buffer][mi][reg]
    uint32_t bf[2][4][2];       // [frag buffer][ni][reg]

#define FRAG_LOAD(fb, bo, j) do {                                           \
        uint32_t aSlot = (uint32_t)((((2 * (j) + akh) ^ asw) & 7) << 4);    \
        uint32_t bSlot = (uint32_t)((((2 * (j) + bkh) ^ bsw) & 7) << 4);    \
        _Pragma("unroll")                                                   \
        for (int mi = 0; mi < 4; mi++) {                                    \
            uint32_t addr = aBase + (bo) + mi * 2048 + aSlot;               \
            asm volatile("ldmatrix.sync.aligned.m8n8.x4.shared.b16 {%0,%1,%2,%3}, [%4];" \
                         : "=r"(af[fb][mi][0]), "=r"(af[fb][mi][1]),        \
                           "=r"(af[fb][mi][2]), "=r"(af[fb][mi][3])         \
                         : "r"(addr));                                      \
        }                                                                   \
        _Pragma("unroll")                                                   \
        for (int p = 0; p < 2; p++) {                                       \
            uint32_t addr = bBase + (bo) + p * 2048 + bSlot;                \
            asm volatile("ldmatrix.sync.aligned.m8n8.x4.shared.b16 {%0,%1,%2,%3}, [%4];" \
                         : "=r"(bf[fb][2*p][0]), "=r"(bf[fb][2*p][1]),      \
                           "=r"(bf[fb][2*p+1][0]), "=r"(bf[fb][2*p+1][1])   \
                         : "r"(addr));                                      \
        }                                                                   \
    } while (0)

#define MMA_J(fb) do {                                                      \
        _Pragma("unroll")                                                   \
        for (int mi = 0; mi < 4; mi++)                                      \
            _Pragma("unroll")                                               \
            for (int ni = 0; ni < 4; ni++) {                                \
                asm volatile(                                               \
                    "mma.sync.aligned.m16n8k16.row.col.f32.bf16.bf16.f32 "  \
                    "{%0,%1,%2,%3}, {%4,%5,%6,%7}, {%8,%9}, {%0,%1,%2,%3};" \
                    : "+f"(acc[mi][ni][0]), "+f"(acc[mi][ni][1]),           \
                      "+f"(acc[mi][ni][2]), "+f"(acc[mi][ni][3])            \
                    : "r"(af[fb][mi][0]), "r"(af[fb][mi][1]),               \
                      "r"(af[fb][mi][2]), "r"(af[fb][mi][3]),               \
                      "r"(bf[fb][ni][0]), "r"(bf[fb][ni][1]));              \
            }                                                               \
    } while (0)

#pragma unroll 1
    for (int s = 0; s < 4; s++) {
        int buf = s % 3;
        if (s < 3) { CP_WAIT1(); } else { CP_WAIT0(); }
        __syncthreads();
        if (s < 2) ISSUE_STAGE(s + 2, (s + 2) % 3);   // buf (s-1)%3: free after barrier

        uint32_t bo = (uint32_t)buf * 16384u;
        FRAG_LOAD(0, bo, 0);
        FRAG_LOAD(1, bo, 1);  MMA_J(0);               // LDSM(j=1) covered by nothing; MMA(0) covers j=1's latency
        FRAG_LOAD(0, bo, 2);  MMA_J(1);               // LDSM(j=2) in flight under 16 MMAs
        FRAG_LOAD(1, bo, 3);  MMA_J(0);
        MMA_J(1);
    }

    // fused column-max over this block's 128 support rows (clamped at 0)
#pragma unroll
    for (int ni = 0; ni < 4; ni++) {
        float mA = acc[0][ni][0], mB = acc[0][ni][1];
#pragma unroll
        for (int mi = 0; mi < 4; mi++) {
            mA = fmaxf(mA, fmaxf(acc[mi][ni][0], acc[mi][ni][2]));
            mB = fmaxf(mB, fmaxf(acc[mi][ni][1], acc[mi][ni][3]));
        }
#pragma unroll
        for (int off = 16; off >= 4; off >>= 1) {
            mA = fmaxf(mA, __shfl_down_sync(0xffffffffu, mA, off));
            mB = fmaxf(mB, __shfl_down_sync(0xffffffffu, mB, off));
        }
        if (lane < 4) {
            int col = qt * 128 + wn * 32 + ni * 8 + 2 * tc;
            int* dst = g_sim + b * NHW + col;
            atomicMax(dst,     __float_as_int(fmaxf(mA, 0.f)));
            atomicMax(dst + 1, __float_as_int(fmaxf(mB, 0.f)));
        }
    }
#undef ISSUE_STAGE
#undef FRAG_LOAD
#undef MMA_J
}

// ---------------- K5: fused per-batch masked mean + log + output ----------------
__global__ void k_lossout(float* __restrict__ out)
{
    __shared__ float rs[1024];
    __shared__ float lb[4];
    int tid = threadIdx.x;
    int b = tid >> 8, t = tid & 255;
    int nq = g_nq[b];
    float s = 0.f;
    for (int j = t; j < nq; j += 256)
        s += __int_as_float(g_sim[b * NHW + j]) * g_qinvc[b * NHW + j];
    rs[tid] = s;
    __syncthreads();
    for (int off = 128; off > 0; off >>= 1) {
        if (t < off) rs[tid] += rs[tid + off];
        __syncthreads();
    }
    if (t == 0) {
        float pc = 0.5f * (rs[tid] / fmaxf((float)nq, 1.f) + 1.f);
        lb[b] = -logf(pc + 1e-8f);
    }
    __syncthreads();
    if (tid == 0)
        out[0] = 0.25f * (lb[0] + lb[1] + lb[2] + lb[3]);
}

// ---------------- launch ----------------
extern "C" void kernel_launch(void* const* d_in, const int* in_sizes, int n_in,
                              void* d_out, int out_size)
{
    const float* Qf   = (const float*)d_in[0];
    const float* Sf   = (const float*)d_in[1];
    const float* Qlab = (const float*)d_in[3];
    const float* Slab = (const float*)d_in[4];
    const float* qbg  = (const float*)d_in[5];
    const float* sbg  = (const float*)d_in[6];
    float* out = (float*)d_out;

    int write_neg = (out_size >= 1 + NB * 2 * NHW * NC) ? 1 : 0;

    // idempotent, host-side, capture-safe; called every launch (no static guards)
    cudaFuncSetAttribute(k_gemm, cudaFuncAttributeMaxDynamicSharedMemorySize, 98304);

    k_prep<<<NB * NHW / 32, 256>>>(Qf, Sf, Qlab, Slab, qbg, sbg);
    k_compact<<<NB, 1024>>>();
    k_pack<<<dim3(NHW / 32, NC / 32, NB), dim3(32, 8)>>>(Qf, Sf, out + 1, write_neg);
    k_gemm<<<dim3(NHW / 128, NHW / 128, NB), 256, 98304>>>();
    k_lossout<<<1, 1024>>>(out);
}

// round 12
// speedup vs baseline: 1.1775x; 1.1775x over previous
#include <cuda_runtime.h>
#include <cuda_bf16.h>
#include <stdint.h>

#define NB 4
#define NC 256
#define NHW 4096
#define NL 512

// ---------------- scratch (no allocations allowed) ----------------
__device__ float    g_Ql   [NB*NHW];
__device__ float    g_Qdis [NB*NHW];
__device__ float    g_Sdis [NB*NHW];
__device__ float    g_winv [NB*NHW];
__device__ float    g_qinv [NB*NHW];
__device__ float    g_qinvc[NB*NHW];
__device__ int      g_qdest[NB*NHW];
__device__ int      g_sdest[NB*NHW];
__device__ int      g_nq[NB], g_ns[NB];
__device__ int      g_sim  [NB*NHW];
__device__ uint32_t g_Ac[NB*NHW*(NC/2)];      // bf16: [b][i][k] row-major (compacted support, pre-scaled)
__device__ uint32_t g_Bc[NB*NHW*(NC/2)];      // bf16: [b][j][k] row-major (compacted query)

static __device__ __forceinline__ uint32_t packbf2(float lo, float hi) {
    __nv_bfloat162 t = __floats2bfloat162_rn(lo, hi);
    return *reinterpret_cast<uint32_t*>(&t);
}

#define CP_ASYNC16(dst, src) \
    asm volatile("cp.async.cg.shared.global [%0], [%1], 16;\n" :: "r"(dst), "l"(src))
#define CP_COMMIT() asm volatile("cp.async.commit_group;\n")
#define CP_WAIT1()  asm volatile("cp.async.wait_group 1;\n" ::: "memory")
#define CP_WAIT0()  asm volatile("cp.async.wait_group 0;\n" ::: "memory")

// ---------------- K1: labels, disrupt masks, column norms (parallel over C) ----------------
__global__ void k_prep(const float* __restrict__ Qf, const float* __restrict__ Sf,
                       const float* __restrict__ Qlab, const float* __restrict__ Slab,
                       const float* __restrict__ qbg, const float* __restrict__ sbg)
{
    __shared__ float sqs[8][33];
    __shared__ float sss[8][33];
    int blk = blockIdx.x;                  // NB*NHW/32 = 512
    int b   = blk >> 7;
    int q0  = (blk & 127) * 32;
    int tx  = threadIdx.x & 31, ty = threadIdx.x >> 5;
    int q   = q0 + tx;

    const float* Qp = Qf + ((size_t)b * NC + ty * 32) * NHW + q;
    const float* Sp = Sf + ((size_t)b * NC + ty * 32) * NHW + q;
    float sq = 0.f, ss = 0.f;
#pragma unroll
    for (int c = 0; c < 32; c++) {
        float v = Qp[(size_t)c * NHW]; sq += v * v;
        float u = Sp[(size_t)c * NHW]; ss += u * u;
    }
    sqs[ty][tx] = sq; sss[ty][tx] = ss;
    __syncthreads();

    if (ty == 0) {
        float tq = 0.f, ts = 0.f;
#pragma unroll
        for (int r = 0; r < 8; r++) { tq += sqs[r][tx]; ts += sss[r][tx]; }
        int idx = b * NHW + q;
        int h = q >> 6, w = q & 63;
        int lab = (h * 8) * NL + (w * 8);              // nearest resize 512->64
        float ql = Qlab[b * NL * NL + lab];
        float sl = Slab[b * NL * NL + lab];
        float qa = (qbg[(b * 2 + 1) * NHW + q] > qbg[(b * 2 + 0) * NHW + q]) ? 1.f : 0.f;
        float sa = (sbg[(b * 2 + 1) * NHW + q] > sbg[(b * 2 + 0) * NHW + q]) ? 1.f : 0.f;
        g_Ql[idx]   = ql;
        g_Qdis[idx] = fmaxf(1.f - qa - ql, 0.f);
        g_Sdis[idx] = fmaxf(1.f - sa - sl, 0.f);
        g_qinv[idx] = (tq > 0.f) ? 1.f / sqrtf(tq) : 0.f;
        g_winv[idx] = (sl != 0.f && ts > 0.f) ? 1.f / sqrtf(ts) : 0.f;
    }
}

// ---------------- K2: per-batch compaction via warp scans + pad/sim init ----------------
__global__ void k_compact()
{
    __shared__ int wq[32], ws[32];
    int b = blockIdx.x, tid = threadIdx.x;
    int lane = tid & 31, wid = tid >> 5;
    int base = b * NHW;

    int qf[4], sf[4];
    int lq = 0, ls = 0;
#pragma unroll
    for (int r = 0; r < 4; r++) {
        int idx = tid * 4 + r;
        qf[r] = (g_Ql[base + idx] == 1.0f);
        sf[r] = (g_winv[base + idx] > 0.f);
        lq += qf[r]; ls += sf[r];
    }
    // warp inclusive scan
    int iq = lq, is = ls;
#pragma unroll
    for (int off = 1; off < 32; off <<= 1) {
        int a = __shfl_up_sync(0xffffffffu, iq, off);
        int c = __shfl_up_sync(0xffffffffu, is, off);
        if (lane >= off) { iq += a; is += c; }
    }
    if (lane == 31) { wq[wid] = iq; ws[wid] = is; }
    __syncthreads();
    if (wid == 0) {
        int vq = wq[lane], vs = ws[lane];
#pragma unroll
        for (int off = 1; off < 32; off <<= 1) {
            int a = __shfl_up_sync(0xffffffffu, vq, off);
            int c = __shfl_up_sync(0xffffffffu, vs, off);
            if (lane >= off) { vq += a; vs += c; }
        }
        wq[lane] = vq; ws[lane] = vs;
    }
    __syncthreads();
    int qex = (wid ? wq[wid - 1] : 0) + iq - lq;
    int sex = (wid ? ws[wid - 1] : 0) + is - ls;
#pragma unroll
    for (int r = 0; r < 4; r++) {
        int idx = tid * 4 + r;
        if (qf[r]) { g_qdest[base + idx] = qex; g_qinvc[base + qex] = g_qinv[base + idx]; }
        else         g_qdest[base + idx] = -1;
        if (sf[r])   g_sdest[base + idx] = sex;
        else         g_sdest[base + idx] = -1;
        qex += qf[r]; sex += sf[r];
    }
    int nq = wq[31], ns = ws[31];
    if (tid == 0) { g_nq[b] = nq; g_ns[b] = ns; }

    for (int i = tid; i < NHW; i += 1024) g_sim[base + i] = 0;

    int nsp = (ns + 127) & ~127;
    for (int i = tid; i < (nsp - ns) * 128; i += 1024) {
        int row = ns + (i >> 7), kp = i & 127;
        g_Ac[((size_t)base + row) * 128 + kp] = 0;
    }
    int nqp = (nq + 127) & ~127;
    for (int i = tid; i < (nqp - nq) * 128; i += 1024) {
        int row = nq + (i >> 7), kp = i & 127;
        g_Bc[((size_t)base + row) * 128 + kp] = 0;
    }
}

// ---------------- K3: negatives + compacted bf16 operand packing ----------------
__global__ void k_pack(const float* __restrict__ Qf, const float* __restrict__ Sf,
                       float* __restrict__ neg, int write_neg)
{
    __shared__ float Qt[32][33];
    __shared__ float St[32][33];
    int b  = blockIdx.z;
    int q0 = blockIdx.x * 32;
    int c0 = blockIdx.y * 32;
    int tx = threadIdx.x, ty = threadIdx.y;

    const float* Qbase = Qf + ((size_t)b * NC + c0) * NHW + q0;
    const float* Sbase = Sf + ((size_t)b * NC + c0) * NHW + q0;
#pragma unroll
    for (int r = 0; r < 4; r++) {
        int c = ty + r * 8;
        Qt[c][tx] = Qbase[(size_t)c * NHW + tx];
        St[c][tx] = Sbase[(size_t)c * NHW + tx];
    }
    __syncthreads();

    if (write_neg) {
#pragma unroll
        for (int r = 0; r < 4; r++) {
            int ql = ty + r * 8;
            int q  = q0 + ql;
            float qd = g_Qdis[b * NHW + q];
            float sd = g_Sdis[b * NHW + q];
            neg[(((size_t)b * 2 + 0) * NHW + q) * NC + c0 + tx] = Qt[tx][ql] * qd;
            neg[(((size_t)b * 2 + 1) * NHW + q) * NC + c0 + tx] = St[tx][ql] * sd;
        }
    }
    int tid = ty * 32 + tx;
    // B operand: [b][j][kp] (compacted queries)
#pragma unroll
    for (int r = 0; r < 2; r++) {
        int ent = tid + r * 256;
        int sl  = ent >> 4;
        int kpl = ent & 15;
        int j = g_qdest[b * NHW + q0 + sl];
        if (j >= 0) {
            g_Bc[((size_t)b * NHW + j) * 128 + c0 / 2 + kpl] =
                packbf2(Qt[2 * kpl][sl], Qt[2 * kpl + 1][sl]);
        }
    }
    // A operand: [b][i][kp] (compacted support, pre-scaled by Sl/|S_col|)
#pragma unroll
    for (int r = 0; r < 2; r++) {
        int ent = tid + r * 256;
        int sl  = ent >> 4;
        int kpl = ent & 15;
        int i = g_sdest[b * NHW + q0 + sl];
        if (i >= 0) {
            float wv = g_winv[b * NHW + q0 + sl];
            g_Ac[((size_t)b * NHW + i) * 128 + c0 / 2 + kpl] =
                packbf2(St[2 * kpl][sl] * wv, St[2 * kpl + 1][sl] * wv);
        }
    }
}

// ---------------- K4: ldmatrix + cp.async bf16 mma GEMM, 64-k stages ----------------
// Tile 128x128, K=256 in 4 stages of 64 k. 3 buffers x 32KB = 96KB dynamic smem.
// COALESCED loader: each cp.async warp-instruction covers 4 FULL 128B lines
// (warp = 4 rows x 128B contiguous) -> 4x fewer L1TEX wavefronts than the old
// 512B-strided 16B-per-thread pattern.
// smem row = 128B, swizzle: phys_chunk = chunk ^ (row & 7)  (conflict-free LDSM octets)
__global__ void __launch_bounds__(256, 2) k_gemm()
{
    extern __shared__ __align__(128) uint4 dsm[];

    int b  = blockIdx.z;
    int qt = blockIdx.x;
    int st = blockIdx.y;
    if (st * 128 >= g_ns[b] || qt * 128 >= g_nq[b]) return;

    int tid  = threadIdx.x;
    int warp = tid >> 5, lane = tid & 31;
    int wm = warp >> 2, wn = warp & 3;      // 2x4 warps -> 64x32 warp tiles
    int tc = lane & 3;

    float acc[4][4][4];
#pragma unroll
    for (int mi = 0; mi < 4; mi++)
#pragma unroll
        for (int ni = 0; ni < 4; ni++)
#pragma unroll
            for (int r = 0; r < 4; r++) acc[mi][ni][r] = 0.f;

    const uint4* gA = (const uint4*)(g_Ac + ((size_t)b * NHW + (size_t)st * 128) * 128);
    const uint4* gB = (const uint4*)(g_Bc + ((size_t)b * NHW + (size_t)qt * 128) * 128);

    uint32_t smem_base = (uint32_t)__cvta_generic_to_shared(dsm);
    const uint32_t B_OFF = 3 * 16384;       // B region after 3 A buffers

    // Coalesced loader mapping: iteration t covers rows t*32..t*32+31.
    // thread -> (rowb = tid>>3 within 32-row group, chunk = tid&7).
    // One warp-instruction = 4 rows x 8 chunks = 4 full 128B lines, contiguous.
    int rowb = tid >> 3;
    int chl  = tid & 7;
    uint32_t dbase = (uint32_t)(rowb * 128 + (((chl ^ rowb) & 7) << 4));
    const uint4* gAs = gA + rowb * 32 + chl;    // row stride 32 uint4 (512B)
    const uint4* gBs = gB + rowb * 32 + chl;

#define ISSUE_STAGE(s, buf) do {                                            \
        uint32_t _o = (uint32_t)(buf) * 16384u + dbase;                     \
        _Pragma("unroll")                                                   \
        for (int t = 0; t < 4; t++) {                                       \
            CP_ASYNC16(smem_base + _o + t * 4096,                           \
                       gAs + (s) * 8 + t * 1024);                           \
            CP_ASYNC16(smem_base + B_OFF + _o + t * 4096,                   \
                       gBs + (s) * 8 + t * 1024);                           \
        }                                                                   \
        CP_COMMIT();                                                        \
    } while (0)

    ISSUE_STAGE(0, 0);
    ISSUE_STAGE(1, 1);

    // LDSM thread->address precompute
    int mt15 = lane & 15;                         // A row within 16 (mi adds 16)
    int akh  = lane >> 4;                         // A k-half (chunk parity)
    int asw  = mt15 & 7;
    uint32_t aBase = smem_base + (wm * 64 + mt15) * 128;
    int ntl  = wn * 32 + (lane & 7) + ((lane >> 4) & 1) * 8;  // B row (p adds 16)
    int bkh  = (lane >> 3) & 1;
    int bsw  = lane & 7;                          // ntl & 7 == lane & 7
    uint32_t bBase = smem_base + B_OFF + ntl * 128;

#pragma unroll 1
    for (int s = 0; s < 4; s++) {
        int buf = s % 3;
        if (s < 3) { CP_WAIT1(); } else { CP_WAIT0(); }
        __syncthreads();
        if (s < 2) ISSUE_STAGE(s + 2, (s + 2) % 3);   // buf (s-1)%3: free after barrier

        uint32_t bo = (uint32_t)buf * 16384u;
#pragma unroll
        for (int j = 0; j < 4; j++) {
            uint32_t aSlot = (uint32_t)((((2 * j + akh) ^ asw) & 7) << 4);
            uint32_t bSlot = (uint32_t)((((2 * j + bkh) ^ bsw) & 7) << 4);
            uint32_t af[4][4];
#pragma unroll
            for (int mi = 0; mi < 4; mi++) {
                uint32_t addr = aBase + bo + mi * 2048 + aSlot;
                asm volatile("ldmatrix.sync.aligned.m8n8.x4.shared.b16 {%0,%1,%2,%3}, [%4];"
                             : "=r"(af[mi][0]), "=r"(af[mi][1]), "=r"(af[mi][2]), "=r"(af[mi][3])
                             : "r"(addr));
            }
            uint32_t bf[4][2];
#pragma unroll
            for (int p = 0; p < 2; p++) {
                uint32_t addr = bBase + bo + p * 2048 + bSlot;
                asm volatile("ldmatrix.sync.aligned.m8n8.x4.shared.b16 {%0,%1,%2,%3}, [%4];"
                             : "=r"(bf[2*p][0]), "=r"(bf[2*p][1]),
                               "=r"(bf[2*p+1][0]), "=r"(bf[2*p+1][1])
                             : "r"(addr));
            }
#pragma unroll
            for (int mi = 0; mi < 4; mi++)
#pragma unroll
                for (int ni = 0; ni < 4; ni++) {
                    asm volatile(
                        "mma.sync.aligned.m16n8k16.row.col.f32.bf16.bf16.f32 "
                        "{%0,%1,%2,%3}, {%4,%5,%6,%7}, {%8,%9}, {%0,%1,%2,%3};"
                        : "+f"(acc[mi][ni][0]), "+f"(acc[mi][ni][1]),
                          "+f"(acc[mi][ni][2]), "+f"(acc[mi][ni][3])
                        : "r"(af[mi][0]), "r"(af[mi][1]), "r"(af[mi][2]), "r"(af[mi][3]),
                          "r"(bf[ni][0]), "r"(bf[ni][1]));
                }
        }
    }

    // fused column-max over this block's 128 support rows (clamped at 0)
#pragma unroll
    for (int ni = 0; ni < 4; ni++) {
        float mA = acc[0][ni][0], mB = acc[0][ni][1];
#pragma unroll
        for (int mi = 0; mi < 4; mi++) {
            mA = fmaxf(mA, fmaxf(acc[mi][ni][0], acc[mi][ni][2]));
            mB = fmaxf(mB, fmaxf(acc[mi][ni][1], acc[mi][ni][3]));
        }
#pragma unroll
        for (int off = 16; off >= 4; off >>= 1) {
            mA = fmaxf(mA, __shfl_down_sync(0xffffffffu, mA, off));
            mB = fmaxf(mB, __shfl_down_sync(0xffffffffu, mB, off));
        }
        if (lane < 4) {
            int col = qt * 128 + wn * 32 + ni * 8 + 2 * tc;
            int* dst = g_sim + b * NHW + col;
            atomicMax(dst,     __float_as_int(fmaxf(mA, 0.f)));
            atomicMax(dst + 1, __float_as_int(fmaxf(mB, 0.f)));
        }
    }
#undef ISSUE_STAGE
}

// ---------------- K5: fused per-batch masked mean + log + output ----------------
__global__ void k_lossout(float* __restrict__ out)
{
    __shared__ float rs[1024];
    __shared__ float lb[4];
    int tid = threadIdx.x;
    int b = tid >> 8, t = tid & 255;
    int nq = g_nq[b];
    float s = 0.f;
    for (int j = t; j < nq; j += 256)
        s += __int_as_float(g_sim[b * NHW + j]) * g_qinvc[b * NHW + j];
    rs[tid] = s;
    __syncthreads();
    for (int off = 128; off > 0; off >>= 1) {
        if (t < off) rs[tid] += rs[tid + off];
        __syncthreads();
    }
    if (t == 0) {
        float pc = 0.5f * (rs[tid] / fmaxf((float)nq, 1.f) + 1.f);
        lb[b] = -logf(pc + 1e-8f);
    }
    __syncthreads();
    if (tid == 0)
        out[0] = 0.25f * (lb[0] + lb[1] + lb[2] + lb[3]);
}

// ---------------- launch ----------------
extern "C" void kernel_launch(void* const* d_in, const int* in_sizes, int n_in,
                              void* d_out, int out_size)
{
    const float* Qf   = (const float*)d_in[0];
    const float* Sf   = (const float*)d_in[1];
    const float* Qlab = (const float*)d_in[3];
    const float* Slab = (const float*)d_in[4];
    const float* qbg  = (const float*)d_in[5];
    const float* sbg  = (const float*)d_in[6];
    float* out = (float*)d_out;

    int write_neg = (out_size >= 1 + NB * 2 * NHW * NC) ? 1 : 0;

    // idempotent, host-side, capture-safe; called every launch (no static guards)
    cudaFuncSetAttribute(k_gemm, cudaFuncAttributeMaxDynamicSharedMemorySize, 98304);

    k_prep<<<NB * NHW / 32, 256>>>(Qf, Sf, Qlab, Slab, qbg, sbg);
    k_compact<<<NB, 1024>>>();
    k_pack<<<dim3(NHW / 32, NC / 32, NB), dim3(32, 8)>>>(Qf, Sf, out + 1, write_neg);
    k_gemm<<<dim3(NHW / 128, NHW / 128, NB), 256, 98304>>>();
    k_lossout<<<1, 1024>>>(out);
}